// round 17
// baseline (speedup 1.0000x reference)
#include <cuda_runtime.h>

// LSTM_60808146977081: B=4096, T=512, I=10, H=32, fp32.
// R15: W_hh moved to SHARED memory (identical across warps -> was 128 wasted
// regs/thread). regs ~246 -> ~115 => 4 CTAs/SM, 4 warps/SMSP, enough warps to
// cover the ~600-cyc per-warp step latency and saturate the FMA pipe.
// Weight smem layout wsh[gate][p4][lane] (transposed) -> conflict-free LDS.128.
// Keeps: tanh.approx activations (0.5-folded sigmoid), xg overlap, 1-step x
// prefetch, per-warp double-buffered h broadcast + __syncwarp.

#define FULL_MASK 0xFFFFFFFFu

__device__ __forceinline__ float2 ffma2(float2 a, float2 b, float2 c) {
    union F2U { float2 f; unsigned long long u; };
    F2U ua, ub, uc, ud;
    ua.f = a; ub.f = b; uc.f = c;
    asm("fma.rn.f32x2 %0, %1, %2, %3;"
        : "=l"(ud.u) : "l"(ua.u), "l"(ub.u), "l"(uc.u));
    return ud.f;
}

__device__ __forceinline__ float tanh_hw(float x) {
    float r;
    asm("tanh.approx.f32 %0, %1;" : "=f"(r) : "f"(x));
    return r;
}

__global__ void __launch_bounds__(128, 4)
lstm_r15(const float* __restrict__ x,
         const float* __restrict__ h0,
         const float* __restrict__ c0,
         const float* __restrict__ W_ih,
         const float* __restrict__ W_hh,
         const float* __restrict__ b_ih,
         const float* __restrict__ b_hh,
         const float* __restrict__ W_lin,
         const float* __restrict__ b_lin,
         float* __restrict__ out)
{
    constexpr int T = 512;
    constexpr int I = 10;

    const int tid  = threadIdx.x;
    const int warp = tid >> 5;
    const int lane = tid & 31;
    const int b    = blockIdx.x * 4 + warp;

    // W_hh (scaled) shared by all 4 warps: [gate][p4][lane] float4.
    // Lane l reads wsh[g][p][l] -> consecutive lanes, consecutive 16B: no conflicts.
    __shared__ float4 wsh[4][8][32];              // 16 KB
    __shared__ float  shh[4][2][32];              // per-warp h bcast, dbl-buffered

    // ---- Cooperative load of W_hh -> smem, activation scale folded ----
    // sigmoid(y) = 0.5*tanh(0.5*y)+0.5 -> scale i,f,o rows by 0.5; g rows by 1.
    for (int idx = tid; idx < 4 * 8 * 32; idx += 128) {
        const int g  = idx >> 8;            // 0..3
        const int p4 = (idx >> 5) & 7;      // 0..7
        const int ln = idx & 31;            // 0..31
        const float s = (g == 2) ? 1.0f : 0.5f;
        const float* wrow = W_hh + (g * 32 + ln) * 32 + p4 * 4;
        wsh[g][p4][ln] = make_float4(wrow[0] * s, wrow[1] * s,
                                     wrow[2] * s, wrow[3] * s);
    }

    // ---- Per-thread W_ih rows + bias (registers; scaled) ----
    float2 wi[4][5];
    float  bias[4];
#pragma unroll
    for (int g = 0; g < 4; g++) {
        const float s = (g == 2) ? 1.0f : 0.5f;
        const int r = g * 32 + lane;
        const float2* wip = reinterpret_cast<const float2*>(W_ih + r * I);
#pragma unroll
        for (int q = 0; q < 5; q++) {
            float2 w = wip[q];
            wi[g][q] = make_float2(w.x * s, w.y * s);
        }
        bias[g] = (b_ih[r] + b_hh[r]) * s;
    }
    const float wl = W_lin[lane];

    float h = h0[b * 32 + lane];
    float c = c0[b * 32 + lane];

    const float2* xw = reinterpret_cast<const float2*>(x + (size_t)b * (T * I));

    // x pipeline: xg = x-gate contribution (incl bias) for step t;
    //             xc = x(t+1), prefetched one step ahead.
    float2 xc[5];
    float2 xg[4];
    {
        float2 x0[5];
#pragma unroll
        for (int q = 0; q < 5; q++) x0[q] = xw[q];        // x(0)
#pragma unroll
        for (int q = 0; q < 5; q++) xc[q] = xw[5 + q];    // x(1)
#pragma unroll
        for (int g = 0; g < 4; g++) {
            xg[g] = make_float2(bias[g], 0.0f);
#pragma unroll
            for (int q = 0; q < 5; q++) xg[g] = ffma2(wi[g][q], x0[q], xg[g]);
        }
    }

    __syncthreads();   // wsh ready

    for (int t = 0; t < T; t++) {
        const int buf = t & 1;
        shh[warp][buf][lane] = h;
        __syncwarp();

        // ---- Recurrent matvec: weights from smem, h broadcast from smem ----
        float2 acc[4];
#pragma unroll
        for (int g = 0; g < 4; g++) acc[g] = xg[g];

        const float4* hp4 = reinterpret_cast<const float4*>(shh[warp][buf]);
#pragma unroll
        for (int p = 0; p < 8; p++) {
            const float4 hv = hp4[p];
            const float2 ha = make_float2(hv.x, hv.y);
            const float2 hb = make_float2(hv.z, hv.w);
#pragma unroll
            for (int g = 0; g < 4; g++) {
                const float4 w4 = wsh[g][p][lane];
                acc[g] = ffma2(make_float2(w4.x, w4.y), ha, acc[g]);
                acc[g] = ffma2(make_float2(w4.z, w4.w), hb, acc[g]);
            }
        }

        const float yi = acc[0].x + acc[0].y;
        const float yf = acc[1].x + acc[1].y;
        const float yg = acc[2].x + acc[2].y;
        const float yo = acc[3].x + acc[3].y;

        // MUFU issues ...
        const float ti = tanh_hw(yi);
        const float tf = tanh_hw(yf);
        const float gc = tanh_hw(yg);
        const float to = tanh_hw(yo);

        // ... overlapped with independent work: xg for t+1 from xc = x(t+1),
        // then prefetch x(t+2) into xc.
#pragma unroll
        for (int g = 0; g < 4; g++) {
            xg[g] = make_float2(bias[g], 0.0f);
#pragma unroll
            for (int q = 0; q < 5; q++) xg[g] = ffma2(wi[g][q], xc[q], xg[g]);
        }
        {
            const int tn = (t + 2 < T) ? t + 2 : T - 1;
            const float2* nxt = xw + (size_t)tn * 5;
#pragma unroll
            for (int q = 0; q < 5; q++) xc[q] = nxt[q];
        }

        // consume tanh results
        const float ig = fmaf(0.5f, ti, 0.5f);
        const float fg = fmaf(0.5f, tf, 0.5f);
        const float og = fmaf(0.5f, to, 0.5f);

        c = fmaf(fg, c, ig * gc);
        h = og * tanh_hw(c);
    }

    // out[b] = sum_k h[k] * W_lin[0,k] + b_lin
    float v = h * wl;
#pragma unroll
    for (int off = 16; off; off >>= 1)
        v += __shfl_xor_sync(FULL_MASK, v, off);
    if (lane == 0) out[b] = v + b_lin[0];
}

extern "C" void kernel_launch(void* const* d_in, const int* in_sizes, int n_in,
                              void* d_out, int out_size)
{
    const float* x     = (const float*)d_in[0];
    const float* h0    = (const float*)d_in[1];
    const float* c0    = (const float*)d_in[2];
    const float* W_ih  = (const float*)d_in[3];
    const float* W_hh  = (const float*)d_in[4];
    const float* b_ih  = (const float*)d_in[5];
    const float* b_hh  = (const float*)d_in[6];
    const float* W_lin = (const float*)d_in[7];
    const float* b_lin = (const float*)d_in[8];
    float* out = (float*)d_out;

    // 4096 batches, 1 per warp, 4 warps per 128-thread block -> 1024 blocks
    lstm_r15<<<1024, 128>>>(x, h0, c0, W_ih, W_hh, b_ih, b_hh,
                            W_lin, b_lin, out);
}